// round 3
// baseline (speedup 1.0000x reference)
#include <cuda_runtime.h>

#define NB   16
#define WIN  128
#define KF   256
#define EMB  256

typedef unsigned long long u64;

// ---- packed f32x2 helpers (sm_100+) ----------------------------------------
#define ADD2(d, a, b) asm("add.rn.f32x2 %0, %1, %2;" : "=l"(d) : "l"(a), "l"(b))
#define FMA2(d, a, b, c) asm("fma.rn.f32x2 %0, %1, %2, %3;" : "=l"(d) : "l"(a), "l"(b), "l"(c))
#define UNPK(lo, hi, v) asm("mov.b64 {%0, %1}, %2;" : "=f"(lo), "=f"(hi) : "l"(v))
#define PK(d, lo, hi) asm("mov.b64 %0, {%1, %2};" : "=l"(d) : "f"(lo), "f"(hi))

// ---------------- device scratch --------------------------------------------
__device__ float g_UI[NB * KF * EMB];        // hi + lin_b
__device__ float g_HJ[NB * KF * EMB];        // hj
__device__ float g_ATT[NB * KF * KF];        // raw e-matrix (incl. attn_bias)
__device__ float g_MS[NB * KF * 4 * 2];      // per (row, j-tile): max, sumexp

// ============================================================================
// gemmA: UI[b,k,e] = sum_w x[b,w,k]*W1[e,w] + lb[e];  HJ = sum_w x*W2
// ============================================================================
#define XP 130
__global__ __launch_bounds__(256)
void gemmA(const float* __restrict__ x, const float* __restrict__ lw,
           const float* __restrict__ lb)
{
    extern __shared__ float sm[];
    float* sXT = sm;                  // [64 k][130]
    float* sW1 = sXT + 64 * XP;       // [64 e][128 w]
    float* sW2 = sW1 + 64 * 128;      // [64 e][128 w]

    const int b  = blockIdx.z;
    const int kt = blockIdx.y * 64;
    const int et = blockIdx.x * 64;
    const int t  = threadIdx.x;

    const float* xb = x + (size_t)b * WIN * KF;
    for (int idx = t; idx < 128 * 64; idx += 256) {
        int w = idx >> 6, kk = idx & 63;
        sXT[kk * XP + w] = xb[w * KF + kt + kk];
    }
    for (int idx = t; idx < 64 * 128; idx += 256) {
        int ee = idx >> 7, w = idx & 127;
        sW1[idx] = lw[(et + ee) * (2 * WIN) + w];
        sW2[idx] = lw[(et + ee) * (2 * WIN) + WIN + w];
    }
    __syncthreads();

    const int tk = t & 15;
    const int te = t >> 4;
    const u64* xp[4];  const u64* w1p[4];  const u64* w2p[4];
    #pragma unroll
    for (int ii = 0; ii < 4; ++ii) xp[ii] = (const u64*)(sXT + (tk + ii * 16) * XP);
    #pragma unroll
    for (int jj = 0; jj < 4; ++jj) {
        w1p[jj] = (const u64*)(sW1 + (te + jj * 16) * 128);
        w2p[jj] = (const u64*)(sW2 + (te + jj * 16) * 128);
    }

    u64 accI[4][4], accJ[4][4];
    #pragma unroll
    for (int ii = 0; ii < 4; ++ii)
        #pragma unroll
        for (int jj = 0; jj < 4; ++jj) { accI[ii][jj] = 0ull; accJ[ii][jj] = 0ull; }

    #pragma unroll 2
    for (int w = 0; w < 64; ++w) {
        u64 xv[4], a1[4], a2[4];
        #pragma unroll
        for (int ii = 0; ii < 4; ++ii) xv[ii] = xp[ii][w];
        #pragma unroll
        for (int jj = 0; jj < 4; ++jj) { a1[jj] = w1p[jj][w]; a2[jj] = w2p[jj][w]; }
        #pragma unroll
        for (int ii = 0; ii < 4; ++ii)
            #pragma unroll
            for (int jj = 0; jj < 4; ++jj) {
                FMA2(accI[ii][jj], xv[ii], a1[jj], accI[ii][jj]);
                FMA2(accJ[ii][jj], xv[ii], a2[jj], accJ[ii][jj]);
            }
    }

    float* sO = sm;
    __syncthreads();
    #pragma unroll
    for (int ii = 0; ii < 4; ++ii)
        #pragma unroll
        for (int jj = 0; jj < 4; ++jj) {
            float lo, hi; UNPK(lo, hi, accI[ii][jj]);
            sO[(tk + ii * 16) * 66 + te + jj * 16] = lo + hi + lb[et + te + jj * 16];
        }
    __syncthreads();
    for (int idx = t; idx < 64 * 64; idx += 256) {
        int r = idx >> 6, c = idx & 63;
        g_UI[((size_t)b * KF + kt + r) * EMB + et + c] = sO[r * 66 + c];
    }
    __syncthreads();
    #pragma unroll
    for (int ii = 0; ii < 4; ++ii)
        #pragma unroll
        for (int jj = 0; jj < 4; ++jj) {
            float lo, hi; UNPK(lo, hi, accJ[ii][jj]);
            sO[(tk + ii * 16) * 66 + te + jj * 16] = lo + hi;
        }
    __syncthreads();
    for (int idx = t; idx < 64 * 64; idx += 256) {
        int r = idx >> 6, c = idx & 63;
        g_HJ[((size_t)b * KF + kt + r) * EMB + et + c] = sO[r * 66 + c];
    }
}

// ============================================================================
// kernB: raw e[b,i,j] (incl AI+AJ+attn_bias) -> g_ATT; per-(row, j-tile)
// softmax partials (max, sumexp) -> g_MS. Row dots computed in-block.
// i-tile 32, j-tile 64, 512 blocks.
// ============================================================================
#define BP 258
__global__ __launch_bounds__(256)
void kernB(const float* __restrict__ a, const float* __restrict__ ab)
{
    extern __shared__ float sm[];
    float* sUI = sm;                   // [32][258]
    float* sHJ = sUI + 32 * BP;        // [64][258]
    float* sA8 = sHJ + 64 * BP;        // [256]
    float* sAI = sA8 + 256;            // [32]
    float* sAJ = sAI + 32;             // [64]

    const int b  = blockIdx.z;
    const int i0 = blockIdx.y * 32;
    const int jt = blockIdx.x;
    const int j0 = jt * 64;
    const int t  = threadIdx.x;

    const float4* gu = (const float4*)(g_UI + ((size_t)b * KF + i0) * EMB);
    for (int idx = t; idx < 32 * 64; idx += 256) {
        int r = idx >> 6, c = idx & 63;
        float4 v = gu[r * 64 + c];
        float2* d = (float2*)(sUI + r * BP + c * 4);
        d[0] = make_float2(v.x, v.y); d[1] = make_float2(v.z, v.w);
    }
    const float4* gh = (const float4*)(g_HJ + ((size_t)b * KF + j0) * EMB);
    for (int idx = t; idx < 64 * 64; idx += 256) {
        int r = idx >> 6, c = idx & 63;
        float4 v = gh[r * 64 + c];
        float2* d = (float2*)(sHJ + r * BP + c * 4);
        d[0] = make_float2(v.x, v.y); d[1] = make_float2(v.z, v.w);
    }
    sA8[t] = 0.8f * a[t];
    __syncthreads();

    // ---- in-block row dots: AI = 0.2*dot(UI,a) = 0.25*dot(UI, 0.8a) --------
    {
        const int warp = t >> 5, lane = t & 31;
        #pragma unroll
        for (int rr = 0; rr < 4; ++rr) {            // UI rows
            int r = warp * 4 + rr;
            float s = 0.f;
            #pragma unroll
            for (int q = 0; q < 8; ++q) s += sUI[r * BP + lane + q * 32] * sA8[lane + q * 32];
            #pragma unroll
            for (int off = 16; off; off >>= 1) s += __shfl_xor_sync(0xffffffffu, s, off);
            if (lane == 0) sAI[r] = 0.25f * s;
        }
        #pragma unroll
        for (int rr = 0; rr < 8; ++rr) {            // HJ rows
            int r = warp * 8 + rr;
            float s = 0.f;
            #pragma unroll
            for (int q = 0; q < 8; ++q) s += sHJ[r * BP + lane + q * 32] * sA8[lane + q * 32];
            #pragma unroll
            for (int off = 16; off; off >>= 1) s += __shfl_xor_sync(0xffffffffu, s, off);
            if (lane == 0) sAJ[r] = 0.25f * s;
        }
    }
    __syncthreads();

    const int ti = t >> 4;   // rows ti, ti+16 (lanes 0-15 / 16-31 split)
    const int jl = t & 15;
    const u64* u0p = (const u64*)(sUI + ti * BP);
    const u64* u1p = (const u64*)(sUI + (ti + 16) * BP);
    const u64* vp[4];
    #pragma unroll
    for (int q = 0; q < 4; ++q) vp[q] = (const u64*)(sHJ + (jl + q * 16) * BP);
    const u64* ap = (const u64*)sA8;

    u64 acc0[4], acc1[4];
    #pragma unroll
    for (int q = 0; q < 4; ++q) { acc0[q] = 0ull; acc1[q] = 0ull; }

    #pragma unroll 2
    for (int e = 0; e < 128; ++e) {
        u64 ae = ap[e], u0 = u0p[e], u1 = u1p[e];
        #pragma unroll
        for (int q = 0; q < 4; ++q) {
            u64 v = vp[q][e];
            u64 s0, s1;
            ADD2(s0, u0, v); ADD2(s1, u1, v);
            float x0, y0, x1, y1;
            UNPK(x0, y0, s0); UNPK(x1, y1, s1);
            x0 = fmaxf(x0, 0.f); y0 = fmaxf(y0, 0.f);
            x1 = fmaxf(x1, 0.f); y1 = fmaxf(y1, 0.f);
            u64 r0, r1; PK(r0, x0, y0); PK(r1, x1, y1);
            FMA2(acc0[q], r0, ae, acc0[q]);
            FMA2(acc1[q], r1, ae, acc1[q]);
        }
    }

    // ---- epilogue: final e values, store raw, softmax partials -------------
    const float ai0 = sAI[ti], ai1 = sAI[ti + 16];
    float v0[4], v1[4];
    #pragma unroll
    for (int q = 0; q < 4; ++q) {
        int jc = jl + q * 16;
        int j  = j0 + jc;
        float lo, hi;
        UNPK(lo, hi, acc0[q]);
        v0[q] = lo + hi + ai0 + sAJ[jc] + ab[(size_t)(i0 + ti) * KF + j];
        UNPK(lo, hi, acc1[q]);
        v1[q] = lo + hi + ai1 + sAJ[jc] + ab[(size_t)(i0 + ti + 16) * KF + j];
        g_ATT[((size_t)b * KF + i0 + ti) * KF + j]      = v0[q];
        g_ATT[((size_t)b * KF + i0 + ti + 16) * KF + j] = v1[q];
    }
    // per-row (over this 64-j tile) max & sumexp; rows live in 16-lane groups
    float m0 = fmaxf(fmaxf(v0[0], v0[1]), fmaxf(v0[2], v0[3]));
    float m1 = fmaxf(fmaxf(v1[0], v1[1]), fmaxf(v1[2], v1[3]));
    #pragma unroll
    for (int off = 8; off; off >>= 1) {
        m0 = fmaxf(m0, __shfl_xor_sync(0xffffffffu, m0, off));
        m1 = fmaxf(m1, __shfl_xor_sync(0xffffffffu, m1, off));
    }
    float s0 = 0.f, s1 = 0.f;
    #pragma unroll
    for (int q = 0; q < 4; ++q) {
        s0 += __expf(v0[q] - m0);
        s1 += __expf(v1[q] - m1);
    }
    #pragma unroll
    for (int off = 8; off; off >>= 1) {
        s0 += __shfl_xor_sync(0xffffffffu, s0, off);
        s1 += __shfl_xor_sync(0xffffffffu, s1, off);
    }
    if (jl == 0) {
        size_t r0i = (size_t)(b * KF + i0 + ti) * 8 + jt * 2;
        size_t r1i = (size_t)(b * KF + i0 + ti + 16) * 8 + jt * 2;
        g_MS[r0i] = m0; g_MS[r0i + 1] = s0;
        g_MS[r1i] = m1; g_MS[r1i + 1] = s1;
    }
}

// ============================================================================
// kernC: combine softmax partials, att = exp(e - M), GEMM over j, scale by
// 1/S, sigmoid. out[b,w,i].
// ============================================================================
#define CP 66
__global__ __launch_bounds__(256)
void kernC(const float* __restrict__ x, float* __restrict__ out)
{
    __shared__ float sAtt[64 * CP];
    __shared__ float sX[32 * CP];
    __shared__ float sM[64];
    __shared__ float sInv[64];

    const int b  = blockIdx.z;
    const int w0 = blockIdx.y * 32;
    const int i0 = blockIdx.x * 64;
    const int t  = threadIdx.x;
    const int il = t & 15;
    const int tw = t >> 4;

    if (t < 64) {
        const float* p = g_MS + (size_t)(b * KF + i0 + t) * 8;
        float m0 = p[0], s0 = p[1], m1 = p[2], s1 = p[3];
        float m2 = p[4], s2 = p[5], m3 = p[6], s3 = p[7];
        float M = fmaxf(fmaxf(m0, m1), fmaxf(m2, m3));
        float S = s0 * __expf(m0 - M) + s1 * __expf(m1 - M)
                + s2 * __expf(m2 - M) + s3 * __expf(m3 - M);
        sM[t] = M;
        sInv[t] = 1.0f / S;
    }

    u64 acc[4][2];
    #pragma unroll
    for (int qi = 0; qi < 4; ++qi) { acc[qi][0] = 0ull; acc[qi][1] = 0ull; }

    for (int jt = 0; jt < 4; ++jt) {
        __syncthreads();
        const int j0 = jt * 64;
        for (int idx = t; idx < 64 * 16; idx += 256) {
            int r = idx >> 4, c = idx & 15;
            float4 v = *(const float4*)(g_ATT + ((size_t)b * KF + i0 + r) * KF + j0 + c * 4);
            float m = sM[r];
            v.x = __expf(v.x - m); v.y = __expf(v.y - m);
            v.z = __expf(v.z - m); v.w = __expf(v.w - m);
            float2* d = (float2*)(sAtt + r * CP + c * 4);
            d[0] = make_float2(v.x, v.y); d[1] = make_float2(v.z, v.w);
        }
        for (int idx = t; idx < 32 * 16; idx += 256) {
            int r = idx >> 4, c = idx & 15;
            float4 v = *(const float4*)(x + ((size_t)b * WIN + w0 + r) * KF + j0 + c * 4);
            float2* d = (float2*)(sX + r * CP + c * 4);
            d[0] = make_float2(v.x, v.y); d[1] = make_float2(v.z, v.w);
        }
        __syncthreads();

        const u64* xp0 = (const u64*)(sX + tw * CP);
        const u64* xp1 = (const u64*)(sX + (tw + 16) * CP);
        const u64* avp[4];
        #pragma unroll
        for (int qi = 0; qi < 4; ++qi) avp[qi] = (const u64*)(sAtt + (il + qi * 16) * CP);

        #pragma unroll 4
        for (int j = 0; j < 32; ++j) {
            u64 x0 = xp0[j], x1 = xp1[j];
            #pragma unroll
            for (int qi = 0; qi < 4; ++qi) {
                u64 av = avp[qi][j];
                FMA2(acc[qi][0], av, x0, acc[qi][0]);
                FMA2(acc[qi][1], av, x1, acc[qi][1]);
            }
        }
    }

    #pragma unroll
    for (int qi = 0; qi < 4; ++qi) {
        int ii = il + qi * 16;
        int i = i0 + ii;
        float inv = sInv[ii];
        #pragma unroll
        for (int qw = 0; qw < 2; ++qw) {
            int w = w0 + tw + qw * 16;
            float lo, hi; UNPK(lo, hi, acc[qi][qw]);
            float s = (lo + hi) * inv;
            out[((size_t)b * WIN + w) * KF + i] = 1.0f / (1.0f + __expf(-s));
        }
    }
}

// ============================================================================
extern "C" void kernel_launch(void* const* d_in, const int* in_sizes, int n_in,
                              void* d_out, int out_size)
{
    const float* x   = (const float*)d_in[0];
    const float* lw  = (const float*)d_in[1];
    const float* lb  = (const float*)d_in[2];
    const float* a   = (const float*)d_in[3];
    const float* ab  = (const float*)d_in[4];
    float* out = (float*)d_out;

    const int smemA = (64 * XP + 64 * 128 + 64 * 128) * 4;
    const int smemB = (32 * BP + 64 * BP + 256 + 32 + 64) * 4;

    cudaFuncSetAttribute(gemmA, cudaFuncAttributeMaxDynamicSharedMemorySize, smemA);
    cudaFuncSetAttribute(kernB, cudaFuncAttributeMaxDynamicSharedMemorySize, smemB);

    gemmA<<<dim3(4, 4, NB), 256, smemA>>>(x, lw, lb);
    kernB<<<dim3(4, 8, NB), 256, smemB>>>(a, ab);
    kernC<<<dim3(4, 4, NB), 256>>>(x, out);
}